// round 5
// baseline (speedup 1.0000x reference)
#include <cuda_runtime.h>
#include <math.h>

#define S 100
#define BATCH 128
#define NW 430500
#define NB 580
#define ES (NW + NB)
#define W12N 25500
#define WOFF2 25500
#define WOFF3 425500

// ---------------- scratch (device globals; no runtime allocation) ----------------
__device__ float g_sigw[NW];
__device__ float g_sigb[NB];
__device__ float g_w1[S * 500];          // per-sample conv1 weights
__device__ float g_w2p[S * 28000];       // per-sample conv2 weights, [ch50][ci20][28pad]
__device__ float g_ball[S * NB];         // per-sample all biases
__device__ float g_h1[S * BATCH * 2880]; // after conv1+relu+pool: [s][b][20][12][12]
__device__ float g_h2[S * BATCH * 800];  // after conv2+relu+pool: [s][b][800] (c*16+y*4+x)
__device__ float g_h3[S * 500 * BATCH];  // after fc1+relu: [s][500][128]
__device__ float g_lsm[S * BATCH * 10];  // per-sample log-softmax

__device__ __forceinline__ float softplusf(float r) {
    return fmaxf(r, 0.0f) + log1pf(expf(-fabsf(r)));
}

// ---------------- kernel 0: softplus(rho) ----------------
__global__ void k_sig(const float* __restrict__ rho_w, const float* __restrict__ rho_b) {
    int i = blockIdx.x * blockDim.x + threadIdx.x;
    if (i < NW) g_sigw[i] = softplusf(rho_w[i]);
    else if (i < NW + NB) g_sigb[i - NW] = softplusf(rho_b[i - NW]);
}

// ---------------- kernel 1: materialize conv weights (repacked) + biases ----------------
__global__ void k_wb(const float* __restrict__ e,
                     const float* __restrict__ mu_w,
                     const float* __restrict__ mu_b) {
    int i = blockIdx.x * blockDim.x + threadIdx.x;
    if (i < S * W12N) {
        int s = i / W12N, j = i % W12N;
        float v = fmaf(g_sigw[j], e[(long)s * ES + j], mu_w[j]);
        if (j < 500) {
            g_w1[s * 500 + j] = v;
        } else {
            int jj = j - 500;
            int ch = jj / 500;
            int r = jj % 500;
            int ci = r / 25, wo = r % 25;
            g_w2p[s * 28000 + ch * 560 + ci * 28 + wo] = v;
        }
    } else {
        int r = i - S * W12N;
        if (r < S * NB) {
            int s = r / NB, j = r % NB;
            g_ball[r] = fmaf(g_sigb[j], e[(long)s * ES + NW + j], mu_b[j]);
        }
    }
}

// ---------------- kernel 2: conv1 + bias + relu + maxpool ----------------
// grid = S*BATCH, block = 288. Thread: one pooled pixel (12x12) x 10 channels.
__global__ void __launch_bounds__(288) k_conv1(const float* __restrict__ x) {
    __shared__ float xs[784];
    __shared__ float ws[500];
    __shared__ float bs[20];
    int blk = blockIdx.x;
    int s = blk / BATCH, b = blk % BATCH;
    int t = threadIdx.x;
    for (int j = t; j < 784; j += 288) xs[j] = x[b * 784 + j];
    for (int j = t; j < 500; j += 288) ws[j] = g_w1[s * 500 + j];
    if (t < 20) bs[t] = g_ball[s * NB + t];
    __syncthreads();

    int pp = t % 144, cg = t / 144;          // cg in {0,1} -> channels cg*10..+9
    int pi = pp / 12, pj = pp % 12;
    float acc[10][4];
#pragma unroll
    for (int k = 0; k < 10; k++) { acc[k][0] = acc[k][1] = acc[k][2] = acc[k][3] = 0.0f; }

    const float* xb = xs + (2 * pi) * 28 + 2 * pj;
#pragma unroll 1
    for (int ky = 0; ky < 5; ky++) {
#pragma unroll
        for (int kx = 0; kx < 5; kx++) {
            float i00 = xb[ky * 28 + kx];
            float i01 = xb[ky * 28 + kx + 1];
            float i10 = xb[(ky + 1) * 28 + kx];
            float i11 = xb[(ky + 1) * 28 + kx + 1];
#pragma unroll
            for (int k = 0; k < 10; k++) {
                float wv = ws[(cg * 10 + k) * 25 + ky * 5 + kx];
                acc[k][0] = fmaf(wv, i00, acc[k][0]);
                acc[k][1] = fmaf(wv, i01, acc[k][1]);
                acc[k][2] = fmaf(wv, i10, acc[k][2]);
                acc[k][3] = fmaf(wv, i11, acc[k][3]);
            }
        }
    }
    float* outp = g_h1 + (long)(s * BATCH + b) * 2880;
#pragma unroll
    for (int k = 0; k < 10; k++) {
        int c = cg * 10 + k;
        float v = fmaxf(fmaxf(acc[k][0], acc[k][1]), fmaxf(acc[k][2], acc[k][3])) + bs[c];
        outp[c * 144 + pp] = fmaxf(v, 0.0f);
    }
}

// ---------------- kernel 3: conv2 + bias + relu + maxpool ----------------
// 6 images/block, block = 960 (160 per image, 30 warps). smem = 181 KB:
// w2p 28000 + bias 56 + ins 6*2880. Weights padded [ch][ci][28].
// 22 groups per sample (21x6 + 1x2 images).
#define CV2_NB 6
#define CV2_G 22                       /* ceil(128/6) */
#define CV2_SMEM_FLOATS (28056 + CV2_NB * 2880)
__global__ void __launch_bounds__(960) k_conv2() {
    extern __shared__ float sm[];
    float* ws  = sm;           // 28000 (padded weights)
    float* bs  = sm + 28000;   // 50 (+6 pad)
    float* ins = sm + 28056;   // 6 * 2880
    int blk = blockIdx.x;
    int s = blk / CV2_G;
    int g = blk % CV2_G;
    int b0 = g * CV2_NB;
    int nimg = (BATCH - b0 < CV2_NB) ? (BATCH - b0) : CV2_NB;
    int t = threadIdx.x;

    // cooperative loads (float4)
    {
        const float4* wp = (const float4*)(g_w2p + s * 28000);
        float4* wd = (float4*)ws;
        for (int j = t; j < 7000; j += 960) wd[j] = wp[j];
        const float4* ip = (const float4*)(g_h1 + (long)(s * BATCH + b0) * 2880);
        float4* id = (float4*)ins;
        int nin = nimg * 720;
        for (int j = t; j < nin; j += 960) id[j] = ip[j];
        if (t < 50) bs[t] = g_ball[s * NB + 20 + t];
    }
    __syncthreads();

    int bl = t / 160;                 // image within block
    int r  = t % 160;
    if (bl >= nimg) return;
    int pp = r % 16, cg = r / 16;     // cg in 0..9 -> channels cg*5..+4
    int pi = pp / 4, pj = pp % 4;
    float acc[5][4];
#pragma unroll
    for (int k = 0; k < 5; k++) { acc[k][0] = acc[k][1] = acc[k][2] = acc[k][3] = 0.0f; }

    const float* ib = ins + bl * 2880 + (2 * pi) * 12 + 2 * pj;
    const float* wbase = ws + cg * 5 * 560;   // 5 channels, stride 560
#pragma unroll 1
    for (int ci = 0; ci < 20; ci++) {
        // cache 6x6 input patch in registers (float2 rows)
        float p[6][6];
        const float* ic = ib + ci * 144;
#pragma unroll
        for (int yy = 0; yy < 6; yy++) {
            float2 a = *(const float2*)(ic + yy * 12);
            float2 c = *(const float2*)(ic + yy * 12 + 2);
            float2 d = *(const float2*)(ic + yy * 12 + 4);
            p[yy][0] = a.x; p[yy][1] = a.y;
            p[yy][2] = c.x; p[yy][3] = c.y;
            p[yy][4] = d.x; p[yy][5] = d.y;
        }

#pragma unroll
        for (int k = 0; k < 5; k++) {
            const float* wc = wbase + k * 560 + ci * 28;
            const float4* wc4 = (const float4*)wc;
#pragma unroll
            for (int kg = 0; kg < 6; kg++) {
                float4 wv = wc4[kg];
                float wa[4] = {wv.x, wv.y, wv.z, wv.w};
#pragma unroll
                for (int q = 0; q < 4; q++) {
                    int wo = kg * 4 + q;
                    int ky = wo / 5, kx = wo % 5;
                    acc[k][0] = fmaf(wa[q], p[ky][kx],       acc[k][0]);
                    acc[k][1] = fmaf(wa[q], p[ky][kx + 1],   acc[k][1]);
                    acc[k][2] = fmaf(wa[q], p[ky + 1][kx],   acc[k][2]);
                    acc[k][3] = fmaf(wa[q], p[ky + 1][kx + 1], acc[k][3]);
                }
            }
            float w24 = wc[24];   // wo = 24 -> ky=4, kx=4
            acc[k][0] = fmaf(w24, p[4][4], acc[k][0]);
            acc[k][1] = fmaf(w24, p[4][5], acc[k][1]);
            acc[k][2] = fmaf(w24, p[5][4], acc[k][2]);
            acc[k][3] = fmaf(w24, p[5][5], acc[k][3]);
        }
    }
    float* outp = g_h2 + (long)(s * BATCH + b0 + bl) * 800;
#pragma unroll
    for (int k = 0; k < 5; k++) {
        int co = cg * 5 + k;
        float v = fmaxf(fmaxf(acc[k][0], acc[k][1]), fmaxf(acc[k][2], acc[k][3])) + bs[co];
        outp[co * 16 + pi * 4 + pj] = fmaxf(v, 0.0f);
    }
}

// ---------------- kernel 4: fc1 (500x800 @ 800x128) + bias + relu ----------------
// grid = (8 mtiles, S), block = 256. BM=64, BN=128, BK=8, thread tile 4x8.
__global__ void __launch_bounds__(256) k_fc1(const float* __restrict__ e,
                                             const float* __restrict__ mu_w) {
    __shared__ float As[8][68];   // padded: transposed A tile [k][m]
    __shared__ float Bs[8][128];  // B tile [k][n]
    int s = blockIdx.y;
    int mt = blockIdx.x;
    int tid = threadIdx.x;
    int tx = tid % 16, ty = tid / 16;
    int m0 = mt * 64;

    const float* eb = e + (long)s * ES + WOFF2;

    int la = tid * 2;              // A: 512 elems, 2 per thread
    int am = la / 8, ak = la % 8;  // (m-local, k-local), ak even
    int bn = tid / 2, bq = (tid % 2) * 4;  // B: one float4 per thread

    float ra0, ra1;
    float rb0, rb1, rb2, rb3;
    {
        int grow = m0 + am;
        if (grow < 500) {
            long ai = (long)grow * 800 + ak;
            ra0 = fmaf(g_sigw[WOFF2 + ai], eb[ai], mu_w[WOFF2 + ai]);
            ra1 = fmaf(g_sigw[WOFF2 + ai + 1], eb[ai + 1], mu_w[WOFF2 + ai + 1]);
        } else { ra0 = 0.0f; ra1 = 0.0f; }
        float4 bv = *(const float4*)(g_h2 + ((long)s * BATCH + bn) * 800 + bq);
        rb0 = bv.x; rb1 = bv.y; rb2 = bv.z; rb3 = bv.w;
    }

    float acc[4][8];
#pragma unroll
    for (int i = 0; i < 4; i++)
#pragma unroll
        for (int j = 0; j < 8; j++) acc[i][j] = 0.0f;

    for (int kt = 0; kt < 100; kt++) {
        As[ak][am] = ra0;
        As[ak + 1][am] = ra1;
        Bs[bq + 0][bn] = rb0;
        Bs[bq + 1][bn] = rb1;
        Bs[bq + 2][bn] = rb2;
        Bs[bq + 3][bn] = rb3;
        __syncthreads();

        if (kt < 99) {
            int k0 = (kt + 1) * 8;
            int grow = m0 + am;
            if (grow < 500) {
                long ai = (long)grow * 800 + k0 + ak;
                ra0 = fmaf(g_sigw[WOFF2 + ai], eb[ai], mu_w[WOFF2 + ai]);
                ra1 = fmaf(g_sigw[WOFF2 + ai + 1], eb[ai + 1], mu_w[WOFF2 + ai + 1]);
            } else { ra0 = 0.0f; ra1 = 0.0f; }
            float4 bv = *(const float4*)(g_h2 + ((long)s * BATCH + bn) * 800 + k0 + bq);
            rb0 = bv.x; rb1 = bv.y; rb2 = bv.z; rb3 = bv.w;
        }

#pragma unroll
        for (int k = 0; k < 8; k++) {
            float a[4], bb[8];
            *(float4*)a = *(const float4*)&As[k][ty * 4];
            *(float4*)bb = *(const float4*)&Bs[k][tx * 8];
            *(float4*)(bb + 4) = *(const float4*)&Bs[k][tx * 8 + 4];
#pragma unroll
            for (int i = 0; i < 4; i++)
#pragma unroll
                for (int j = 0; j < 8; j++)
                    acc[i][j] = fmaf(a[i], bb[j], acc[i][j]);
        }
        __syncthreads();
    }

#pragma unroll
    for (int i = 0; i < 4; i++) {
        int m = m0 + ty * 4 + i;
        if (m < 500) {
            float bias = g_ball[s * NB + 70 + m];
            float* op = g_h3 + ((long)s * 500 + m) * BATCH + tx * 8;
#pragma unroll
            for (int j = 0; j < 8; j++) {
                op[j] = fmaxf(acc[i][j] + bias, 0.0f);
            }
        }
    }
}

// ---------------- kernel 5: fc2 + bias + log_softmax ----------------
__global__ void __launch_bounds__(128) k_fc2(const float* __restrict__ e,
                                             const float* __restrict__ mu_w) {
    __shared__ float ws[5000];
    __shared__ float bs[10];
    int s = blockIdx.x;
    int t = threadIdx.x;
    for (int j = t; j < 5000; j += 128) {
        long gi = (long)WOFF3 + j;
        ws[j] = fmaf(g_sigw[gi], e[(long)s * ES + gi], mu_w[gi]);
    }
    if (t < 10) bs[t] = g_ball[s * NB + 570 + t];
    __syncthreads();

    float acc[10];
#pragma unroll
    for (int o = 0; o < 10; o++) acc[o] = bs[o];

    const float* hp = g_h3 + (long)s * 500 * BATCH + t;
    for (int i = 0; i < 500; i++) {
        float v = hp[(long)i * BATCH];
#pragma unroll
        for (int o = 0; o < 10; o++) acc[o] = fmaf(ws[o * 500 + i], v, acc[o]);
    }

    float m = acc[0];
#pragma unroll
    for (int o = 1; o < 10; o++) m = fmaxf(m, acc[o]);
    float sum = 0.0f;
#pragma unroll
    for (int o = 0; o < 10; o++) sum += expf(acc[o] - m);
    float lse = m + logf(sum);

    float* op = g_lsm + ((long)s * BATCH + t) * 10;
#pragma unroll
    for (int o = 0; o < 10; o++) op[o] = acc[o] - lse;
}

// ---------------- kernel 6: deterministic mean over samples ----------------
__global__ void k_reduce(float* __restrict__ out) {
    int idx = blockIdx.x * blockDim.x + threadIdx.x;
    if (idx >= BATCH * 10) return;
    int b = idx / 10, o = idx % 10;
    float acc = 0.0f;
    for (int s = 0; s < S; s++) acc += g_lsm[((long)s * BATCH + b) * 10 + o];
    out[idx] = acc * (1.0f / (float)S);
}

// ---------------- launch ----------------
extern "C" void kernel_launch(void* const* d_in, const int* in_sizes, int n_in,
                              void* d_out, int out_size) {
    const float* x     = (const float*)d_in[0];
    const float* e     = (const float*)d_in[1];
    const float* mu_w  = (const float*)d_in[2];
    const float* rho_w = (const float*)d_in[3];
    const float* mu_b  = (const float*)d_in[4];
    const float* rho_b = (const float*)d_in[5];
    float* out = (float*)d_out;

    static int smem_set = 0;
    if (!smem_set) {
        cudaFuncSetAttribute(k_conv2, cudaFuncAttributeMaxDynamicSharedMemorySize,
                             CV2_SMEM_FLOATS * 4);
        smem_set = 1;
    }

    k_sig<<<(ES + 255) / 256, 256>>>(rho_w, rho_b);

    int wb_total = S * W12N + S * NB;
    k_wb<<<(wb_total + 255) / 256, 256>>>(e, mu_w, mu_b);

    k_conv1<<<S * BATCH, 288>>>(x);
    k_conv2<<<S * CV2_G, 960, CV2_SMEM_FLOATS * 4>>>();

    dim3 g1(8, S);
    k_fc1<<<g1, 256>>>(e, mu_w);
    k_fc2<<<S, 128>>>(e, mu_w);
    k_reduce<<<10, 128>>>(out);
}

// round 6
// speedup vs baseline: 1.6085x; 1.6085x over previous
#include <cuda_runtime.h>
#include <math.h>
#include <stdint.h>

#define S 100
#define BATCH 128
#define NW 430500
#define NB 580
#define ES (NW + NB)
#define W12N 25500
#define WOFF2 25500
#define WOFF3 425500

// ---------------- scratch (device globals; no runtime allocation) ----------------
__device__ float g_sigw[NW];
__device__ float g_sigb[NB];
__device__ float g_w1[S * 500];           // per-sample conv1 weights
__device__ float g_w2p[S * 33280];        // per-sample conv2 weights, [k=ci*32+kk][52 ch pad], tf32-rounded
__device__ float g_ball[S * NB];          // per-sample all biases
__device__ float g_h1[S * BATCH * 2880];  // after conv1+relu+pool: [s][b][20][12][12]
__device__ float g_h2[S * BATCH * 800];   // after conv2+relu+pool: [s][b][800] (c*16+y*4+x)
__device__ float g_h3[S * 500 * BATCH];   // after fc1+relu: [s][500][128]
__device__ float g_lsm[S * BATCH * 10];   // per-sample log-softmax

__device__ __forceinline__ float softplusf(float r) {
    return fmaxf(r, 0.0f) + log1pf(expf(-fabsf(r)));
}

__device__ __forceinline__ uint32_t f2tf32(float v) {
    uint32_t o;
    asm("cvt.rna.tf32.f32 %0, %1;" : "=r"(o) : "f"(v));
    return o;
}

// ---------------- kernel 0: softplus(rho) ----------------
__global__ void k_sig(const float* __restrict__ rho_w, const float* __restrict__ rho_b) {
    int i = blockIdx.x * blockDim.x + threadIdx.x;
    if (i < NW) g_sigw[i] = softplusf(rho_w[i]);
    else if (i < NW + NB) g_sigb[i - NW] = softplusf(rho_b[i - NW]);
}

// ---------------- kernel 1: materialize conv weights + biases ----------------
// conv2 weights stored tf32-rounded in GEMM layout [k=ci*32+(ky*5+kx)][52 ch pad].
// Pad entries (kk 25..31, ch 50..51) stay zero (device globals are zero-initialized
// and never written).
__global__ void k_wb(const float* __restrict__ e,
                     const float* __restrict__ mu_w,
                     const float* __restrict__ mu_b) {
    int i = blockIdx.x * blockDim.x + threadIdx.x;
    if (i < S * W12N) {
        int s = i / W12N, j = i % W12N;
        float v = fmaf(g_sigw[j], e[(long)s * ES + j], mu_w[j]);
        if (j < 500) {
            g_w1[s * 500 + j] = v;
        } else {
            int jj = j - 500;
            int ch = jj / 500;
            int r = jj % 500;
            int ci = r / 25, wo = r % 25;
            g_w2p[(long)s * 33280 + (ci * 32 + wo) * 52 + ch] = __uint_as_float(f2tf32(v));
        }
    } else {
        int r = i - S * W12N;
        if (r < S * NB) {
            int s = r / NB, j = r % NB;
            g_ball[r] = fmaf(g_sigb[j], e[(long)s * ES + NW + j], mu_b[j]);
        }
    }
}

// ---------------- kernel 2: conv1 + bias + relu + maxpool ----------------
__global__ void __launch_bounds__(288) k_conv1(const float* __restrict__ x) {
    __shared__ float xs[784];
    __shared__ float ws[500];
    __shared__ float bs[20];
    int blk = blockIdx.x;
    int s = blk / BATCH, b = blk % BATCH;
    int t = threadIdx.x;
    for (int j = t; j < 784; j += 288) xs[j] = x[b * 784 + j];
    for (int j = t; j < 500; j += 288) ws[j] = g_w1[s * 500 + j];
    if (t < 20) bs[t] = g_ball[s * NB + t];
    __syncthreads();

    int pp = t % 144, cg = t / 144;
    int pi = pp / 12, pj = pp % 12;
    float acc[10][4];
#pragma unroll
    for (int k = 0; k < 10; k++) { acc[k][0] = acc[k][1] = acc[k][2] = acc[k][3] = 0.0f; }

    const float* xb = xs + (2 * pi) * 28 + 2 * pj;
#pragma unroll 1
    for (int ky = 0; ky < 5; ky++) {
#pragma unroll
        for (int kx = 0; kx < 5; kx++) {
            float i00 = xb[ky * 28 + kx];
            float i01 = xb[ky * 28 + kx + 1];
            float i10 = xb[(ky + 1) * 28 + kx];
            float i11 = xb[(ky + 1) * 28 + kx + 1];
#pragma unroll
            for (int k = 0; k < 10; k++) {
                float wv = ws[(cg * 10 + k) * 25 + ky * 5 + kx];
                acc[k][0] = fmaf(wv, i00, acc[k][0]);
                acc[k][1] = fmaf(wv, i01, acc[k][1]);
                acc[k][2] = fmaf(wv, i10, acc[k][2]);
                acc[k][3] = fmaf(wv, i11, acc[k][3]);
            }
        }
    }
    float* outp = g_h1 + (long)(s * BATCH + b) * 2880;
#pragma unroll
    for (int k = 0; k < 10; k++) {
        int c = cg * 10 + k;
        float v = fmaxf(fmaxf(acc[k][0], acc[k][1]), fmaxf(acc[k][2], acc[k][3])) + bs[c];
        outp[c * 144 + pp] = fmaxf(v, 0.0f);
    }
}

// ---------------- kernel 3: conv2 as tf32 tensor-core implicit GEMM ----------------
// One block = (sample s, 4 images). C[64][256] = W[64][640] x col[640][256].
// K padded: 32 per input channel (kk = ky*5+kx, 25..31 zero).
// Warp tile M32 x N64 x K32 per ci; 8 warps (2 m-rows x 4 n-cols).
// Epilogue: C -> smem, fused bias + relu + 2x2 maxpool -> g_h2.
#define WSM_F (640 * 56)     /* A: [k640][56], cols 50..51 zero, 52..55 never read */
#define BSM_F (32 * 264)     /* B: [k32][264], rows 25..31 zero */
#define INS_F (4 * 2880)
#define CV2T_SMEM ((WSM_F + BSM_F + INS_F) * 4)

__global__ void __launch_bounds__(256) k_conv2_tc() {
    extern __shared__ float sm[];
    float* Wsm = sm;                    // 35840
    float* Bsm = sm + WSM_F;            // 8448
    float* ins = sm + WSM_F + BSM_F;    // 11520
    int blk = blockIdx.x;
    int s = blk >> 5;
    int b0 = (blk & 31) * 4;
    int t = threadIdx.x;
    int lane = t & 31, w = t >> 5;
    int g = lane >> 2, tig = lane & 3;

    // cooperative loads
    {
        const float4* wp = (const float4*)(g_w2p + (long)s * 33280);
        for (int j = t; j < 8320; j += 256) {
            int k = j / 13, c = j % 13;
            *(float4*)(Wsm + k * 56 + c * 4) = wp[j];
        }
        const float4* ip = (const float4*)(g_h1 + (long)(s * BATCH + b0) * 2880);
        float4* id = (float4*)ins;
        for (int j = t; j < 2880; j += 256) id[j] = ip[j];
        float4 z = {0.0f, 0.0f, 0.0f, 0.0f};
        float4* bz = (float4*)Bsm;
        for (int j = t; j < BSM_F / 4; j += 256) bz[j] = z;
    }

    int m0 = (w & 1) * 32;
    int n0 = (w >> 1) * 64;

    // A row indices with clamp to zero-column 50 for m >= 50
    int mA[2][2];
#pragma unroll
    for (int mt = 0; mt < 2; mt++) {
        int r0 = m0 + mt * 16 + g;
        int r1 = r0 + 8;
        mA[mt][0] = (r0 < 50) ? r0 : 50;
        mA[mt][1] = (r1 < 50) ? r1 : 50;
    }

    float acc[2][8][4];
#pragma unroll
    for (int mt = 0; mt < 2; mt++)
#pragma unroll
        for (int nt = 0; nt < 8; nt++)
#pragma unroll
            for (int q = 0; q < 4; q++) acc[mt][nt][q] = 0.0f;

    // per-thread im2col build params (thread t owns column n = t)
    int bimg = t >> 6;
    int by = (t >> 3) & 7;
    int bx = t & 7;
    const float* bsrc = ins + bimg * 2880 + by * 12 + bx;

    __syncthreads();

    for (int ci = 0; ci < 20; ci++) {
        // build B rows 0..24 for this input channel
        const float* src = bsrc + ci * 144;
#pragma unroll
        for (int ky = 0; ky < 5; ky++)
#pragma unroll
            for (int kx = 0; kx < 5; kx++) {
                Bsm[(ky * 5 + kx) * 264 + t] = __uint_as_float(f2tf32(src[ky * 12 + kx]));
            }
        __syncthreads();

#pragma unroll
        for (int kt = 0; kt < 4; kt++) {
            const float* Wk = Wsm + (ci * 32 + kt * 8 + tig) * 56;
            uint32_t a[2][4];
#pragma unroll
            for (int mt = 0; mt < 2; mt++) {
                a[mt][0] = __float_as_uint(Wk[mA[mt][0]]);
                a[mt][1] = __float_as_uint(Wk[mA[mt][1]]);
                a[mt][2] = __float_as_uint(Wk[4 * 56 + mA[mt][0]]);
                a[mt][3] = __float_as_uint(Wk[4 * 56 + mA[mt][1]]);
            }
            const float* Bk = Bsm + (kt * 8 + tig) * 264 + n0 + g;
#pragma unroll
            for (int nt = 0; nt < 8; nt++) {
                uint32_t br0 = __float_as_uint(Bk[nt * 8]);
                uint32_t br1 = __float_as_uint(Bk[4 * 264 + nt * 8]);
#pragma unroll
                for (int mt = 0; mt < 2; mt++) {
                    asm volatile(
                        "mma.sync.aligned.m16n8k8.row.col.f32.tf32.tf32.f32 "
                        "{%0,%1,%2,%3}, {%4,%5,%6,%7}, {%8,%9}, {%0,%1,%2,%3};\n"
                        : "+f"(acc[mt][nt][0]), "+f"(acc[mt][nt][1]),
                          "+f"(acc[mt][nt][2]), "+f"(acc[mt][nt][3])
                        : "r"(a[mt][0]), "r"(a[mt][1]), "r"(a[mt][2]), "r"(a[mt][3]),
                          "r"(br0), "r"(br1));
                }
            }
        }
        __syncthreads();
    }

    // epilogue: C fragments -> smem (reuse Wsm region; all mma reads done)
    float* Csm = Wsm;   // [64][264]
#pragma unroll
    for (int mt = 0; mt < 2; mt++) {
        int r0 = m0 + mt * 16 + g;
#pragma unroll
        for (int nt = 0; nt < 8; nt++) {
            int c0 = n0 + nt * 8 + 2 * tig;
            Csm[r0 * 264 + c0]           = acc[mt][nt][0];
            Csm[r0 * 264 + c0 + 1]       = acc[mt][nt][1];
            Csm[(r0 + 8) * 264 + c0]     = acc[mt][nt][2];
            Csm[(r0 + 8) * 264 + c0 + 1] = acc[mt][nt][3];
        }
    }
    __syncthreads();

    // bias + relu + 2x2 maxpool -> g_h2
    for (int idx = t; idx < 3200; idx += 256) {
        int ch = idx >> 6;
        int r = idx & 63;
        int img = r >> 4;
        int pp = r & 15;
        int py = pp >> 2, px = pp & 3;
        int n = img * 64 + (2 * py) * 8 + 2 * px;
        float v0 = Csm[ch * 264 + n],     v1 = Csm[ch * 264 + n + 1];
        float v2 = Csm[ch * 264 + n + 8], v3 = Csm[ch * 264 + n + 9];
        float v = fmaxf(fmaxf(v0, v1), fmaxf(v2, v3)) + g_ball[s * NB + 20 + ch];
        g_h2[(long)(s * BATCH + b0 + img) * 800 + ch * 16 + pp] = fmaxf(v, 0.0f);
    }
}

// ---------------- kernel 4: fc1 (500x800 @ 800x128) + bias + relu ----------------
__global__ void __launch_bounds__(256) k_fc1(const float* __restrict__ e,
                                             const float* __restrict__ mu_w) {
    __shared__ float As[8][68];
    __shared__ float Bs[8][128];
    int s = blockIdx.y;
    int mt = blockIdx.x;
    int tid = threadIdx.x;
    int tx = tid % 16, ty = tid / 16;
    int m0 = mt * 64;

    const float* eb = e + (long)s * ES + WOFF2;

    int la = tid * 2;
    int am = la / 8, ak = la % 8;
    int bn = tid / 2, bq = (tid % 2) * 4;

    float ra0, ra1;
    float rb0, rb1, rb2, rb3;
    {
        int grow = m0 + am;
        if (grow < 500) {
            long ai = (long)grow * 800 + ak;
            ra0 = fmaf(g_sigw[WOFF2 + ai], eb[ai], mu_w[WOFF2 + ai]);
            ra1 = fmaf(g_sigw[WOFF2 + ai + 1], eb[ai + 1], mu_w[WOFF2 + ai + 1]);
        } else { ra0 = 0.0f; ra1 = 0.0f; }
        float4 bv = *(const float4*)(g_h2 + ((long)s * BATCH + bn) * 800 + bq);
        rb0 = bv.x; rb1 = bv.y; rb2 = bv.z; rb3 = bv.w;
    }

    float acc[4][8];
#pragma unroll
    for (int i = 0; i < 4; i++)
#pragma unroll
        for (int j = 0; j < 8; j++) acc[i][j] = 0.0f;

    for (int kt = 0; kt < 100; kt++) {
        As[ak][am] = ra0;
        As[ak + 1][am] = ra1;
        Bs[bq + 0][bn] = rb0;
        Bs[bq + 1][bn] = rb1;
        Bs[bq + 2][bn] = rb2;
        Bs[bq + 3][bn] = rb3;
        __syncthreads();

        if (kt < 99) {
            int k0 = (kt + 1) * 8;
            int grow = m0 + am;
            if (grow < 500) {
                long ai = (long)grow * 800 + k0 + ak;
                ra0 = fmaf(g_sigw[WOFF2 + ai], eb[ai], mu_w[WOFF2 + ai]);
                ra1 = fmaf(g_sigw[WOFF2 + ai + 1], eb[ai + 1], mu_w[WOFF2 + ai + 1]);
            } else { ra0 = 0.0f; ra1 = 0.0f; }
            float4 bv = *(const float4*)(g_h2 + ((long)s * BATCH + bn) * 800 + k0 + bq);
            rb0 = bv.x; rb1 = bv.y; rb2 = bv.z; rb3 = bv.w;
        }

#pragma unroll
        for (int k = 0; k < 8; k++) {
            float a[4], bb[8];
            *(float4*)a = *(const float4*)&As[k][ty * 4];
            *(float4*)bb = *(const float4*)&Bs[k][tx * 8];
            *(float4*)(bb + 4) = *(const float4*)&Bs[k][tx * 8 + 4];
#pragma unroll
            for (int i = 0; i < 4; i++)
#pragma unroll
                for (int j = 0; j < 8; j++)
                    acc[i][j] = fmaf(a[i], bb[j], acc[i][j]);
        }
        __syncthreads();
    }

#pragma unroll
    for (int i = 0; i < 4; i++) {
        int m = m0 + ty * 4 + i;
        if (m < 500) {
            float bias = g_ball[s * NB + 70 + m];
            float* op = g_h3 + ((long)s * 500 + m) * BATCH + tx * 8;
#pragma unroll
            for (int j = 0; j < 8; j++) {
                op[j] = fmaxf(acc[i][j] + bias, 0.0f);
            }
        }
    }
}

// ---------------- kernel 5: fc2 + bias + log_softmax ----------------
__global__ void __launch_bounds__(128) k_fc2(const float* __restrict__ e,
                                             const float* __restrict__ mu_w) {
    __shared__ float ws[5000];
    __shared__ float bs[10];
    int s = blockIdx.x;
    int t = threadIdx.x;
    for (int j = t; j < 5000; j += 128) {
        long gi = (long)WOFF3 + j;
        ws[j] = fmaf(g_sigw[gi], e[(long)s * ES + gi], mu_w[gi]);
    }
    if (t < 10) bs[t] = g_ball[s * NB + 570 + t];
    __syncthreads();

    float acc[10];
#pragma unroll
    for (int o = 0; o < 10; o++) acc[o] = bs[o];

    const float* hp = g_h3 + (long)s * 500 * BATCH + t;
    for (int i = 0; i < 500; i++) {
        float v = hp[(long)i * BATCH];
#pragma unroll
        for (int o = 0; o < 10; o++) acc[o] = fmaf(ws[o * 500 + i], v, acc[o]);
    }

    float m = acc[0];
#pragma unroll
    for (int o = 1; o < 10; o++) m = fmaxf(m, acc[o]);
    float sum = 0.0f;
#pragma unroll
    for (int o = 0; o < 10; o++) sum += expf(acc[o] - m);
    float lse = m + logf(sum);

    float* op = g_lsm + ((long)s * BATCH + t) * 10;
#pragma unroll
    for (int o = 0; o < 10; o++) op[o] = acc[o] - lse;
}

// ---------------- kernel 6: deterministic mean over samples ----------------
__global__ void k_reduce(float* __restrict__ out) {
    int idx = blockIdx.x * blockDim.x + threadIdx.x;
    if (idx >= BATCH * 10) return;
    int b = idx / 10, o = idx % 10;
    float acc = 0.0f;
    for (int s = 0; s < S; s++) acc += g_lsm[((long)s * BATCH + b) * 10 + o];
    out[idx] = acc * (1.0f / (float)S);
}

// ---------------- launch ----------------
extern "C" void kernel_launch(void* const* d_in, const int* in_sizes, int n_in,
                              void* d_out, int out_size) {
    const float* x     = (const float*)d_in[0];
    const float* e     = (const float*)d_in[1];
    const float* mu_w  = (const float*)d_in[2];
    const float* rho_w = (const float*)d_in[3];
    const float* mu_b  = (const float*)d_in[4];
    const float* rho_b = (const float*)d_in[5];
    float* out = (float*)d_out;

    static int smem_set = 0;
    if (!smem_set) {
        cudaFuncSetAttribute(k_conv2_tc, cudaFuncAttributeMaxDynamicSharedMemorySize,
                             CV2T_SMEM);
        smem_set = 1;
    }

    k_sig<<<(ES + 255) / 256, 256>>>(rho_w, rho_b);

    int wb_total = S * W12N + S * NB;
    k_wb<<<(wb_total + 255) / 256, 256>>>(e, mu_w, mu_b);

    k_conv1<<<S * BATCH, 288>>>(x);
    k_conv2_tc<<<S * 32, 256, CV2T_SMEM>>>();

    dim3 g1(8, S);
    k_fc1<<<g1, 256>>>(e, mu_w);
    k_fc2<<<S, 128>>>(e, mu_w);
    k_reduce<<<10, 128>>>(out);
}

// round 7
// speedup vs baseline: 2.0440x; 1.2708x over previous
#include <cuda_runtime.h>
#include <math.h>
#include <stdint.h>

#define S 100
#define BATCH 128
#define NW 430500
#define NB 580
#define ES (NW + NB)
#define W12N 25500
#define WOFF2 25500
#define WOFF3 425500

// ---------------- scratch (device globals; no runtime allocation) ----------------
__device__ float g_sigw[NW];
__device__ float g_sigb[NB];
__device__ float g_w1[S * 500];           // per-sample conv1 weights
__device__ float g_w2p[S * 33280];        // per-sample conv2 weights, [k=ci*32+kk][52 ch pad], tf32-rounded
__device__ float g_ball[S * NB];          // per-sample all biases
__device__ float g_h1[S * BATCH * 2880];  // after conv1+relu+pool: [s][b][20][12][12]
__device__ float g_h2[S * BATCH * 800];   // after conv2+relu+pool: [s][b][800] (c*16+y*4+x)
__device__ float g_h3[S * 500 * BATCH];   // after fc1+relu: [s][500][128]
__device__ float g_lsm[S * BATCH * 10];   // per-sample log-softmax

__device__ __forceinline__ float softplusf(float r) {
    return fmaxf(r, 0.0f) + log1pf(expf(-fabsf(r)));
}

__device__ __forceinline__ uint32_t f2tf32(float v) {
    uint32_t o;
    asm("cvt.rna.tf32.f32 %0, %1;" : "=r"(o) : "f"(v));
    return o;
}

// ---------------- kernel 0: softplus(rho) ----------------
__global__ void k_sig(const float* __restrict__ rho_w, const float* __restrict__ rho_b) {
    int i = blockIdx.x * blockDim.x + threadIdx.x;
    if (i < NW) g_sigw[i] = softplusf(rho_w[i]);
    else if (i < NW + NB) g_sigb[i - NW] = softplusf(rho_b[i - NW]);
}

// ---------------- kernel 1: materialize conv weights + biases ----------------
// conv2 weights tf32-rounded, GEMM layout [k=ci*32+(ky*5+kx)][52 ch pad].
// Pad entries (kk 25..31, ch 50..51) stay zero (zero-initialized device globals,
// never written) -> B fragments for those k-rows may be garbage (A=0 kills them).
__global__ void k_wb(const float* __restrict__ e,
                     const float* __restrict__ mu_w,
                     const float* __restrict__ mu_b) {
    int i = blockIdx.x * blockDim.x + threadIdx.x;
    if (i < S * W12N) {
        int s = i / W12N, j = i % W12N;
        float v = fmaf(g_sigw[j], e[(long)s * ES + j], mu_w[j]);
        if (j < 500) {
            g_w1[s * 500 + j] = v;
        } else {
            int jj = j - 500;
            int ch = jj / 500;
            int r = jj % 500;
            int ci = r / 25, wo = r % 25;
            g_w2p[(long)s * 33280 + (ci * 32 + wo) * 52 + ch] = __uint_as_float(f2tf32(v));
        }
    } else {
        int r = i - S * W12N;
        if (r < S * NB) {
            int s = r / NB, j = r % NB;
            g_ball[r] = fmaf(g_sigb[j], e[(long)s * ES + NW + j], mu_b[j]);
        }
    }
}

// ---------------- kernel 2: conv1 + bias + relu + maxpool ----------------
__global__ void __launch_bounds__(288) k_conv1(const float* __restrict__ x) {
    __shared__ float xs[784];
    __shared__ float ws[500];
    __shared__ float bs[20];
    int blk = blockIdx.x;
    int s = blk / BATCH, b = blk % BATCH;
    int t = threadIdx.x;
    for (int j = t; j < 784; j += 288) xs[j] = x[b * 784 + j];
    for (int j = t; j < 500; j += 288) ws[j] = g_w1[s * 500 + j];
    if (t < 20) bs[t] = g_ball[s * NB + t];
    __syncthreads();

    int pp = t % 144, cg = t / 144;
    int pi = pp / 12, pj = pp % 12;
    float acc[10][4];
#pragma unroll
    for (int k = 0; k < 10; k++) { acc[k][0] = acc[k][1] = acc[k][2] = acc[k][3] = 0.0f; }

    const float* xb = xs + (2 * pi) * 28 + 2 * pj;
#pragma unroll 1
    for (int ky = 0; ky < 5; ky++) {
#pragma unroll
        for (int kx = 0; kx < 5; kx++) {
            float i00 = xb[ky * 28 + kx];
            float i01 = xb[ky * 28 + kx + 1];
            float i10 = xb[(ky + 1) * 28 + kx];
            float i11 = xb[(ky + 1) * 28 + kx + 1];
#pragma unroll
            for (int k = 0; k < 10; k++) {
                float wv = ws[(cg * 10 + k) * 25 + ky * 5 + kx];
                acc[k][0] = fmaf(wv, i00, acc[k][0]);
                acc[k][1] = fmaf(wv, i01, acc[k][1]);
                acc[k][2] = fmaf(wv, i10, acc[k][2]);
                acc[k][3] = fmaf(wv, i11, acc[k][3]);
            }
        }
    }
    float* outp = g_h1 + (long)(s * BATCH + b) * 2880;
#pragma unroll
    for (int k = 0; k < 10; k++) {
        int c = cg * 10 + k;
        float v = fmaxf(fmaxf(acc[k][0], acc[k][1]), fmaxf(acc[k][2], acc[k][3])) + bs[c];
        outp[c * 144 + pp] = fmaxf(v, 0.0f);
    }
}

// ---------------- kernel 3: conv2 tf32 implicit GEMM, direct B gather ----------------
// One block = (sample, 8 images), 512 threads / 16 warps.
// C[64][512] = W[64][640] x col[640][512]; no im2col materialization:
// B fragments gathered straight from the input tile in smem (addresses clamped
// for padded k-rows; corresponding A rows are zero). NO syncs in the mainloop.
// smem: W [640][52] = 33280 fl + input 8*2880 = 23040 fl -> 225280 B.
#define CV2_WF (640 * 52)
#define CV2_IF (8 * 2880)
#define CV2T_SMEM ((CV2_WF + CV2_IF) * 4)

__global__ void __launch_bounds__(512) k_conv2_tc() {
    extern __shared__ float sm[];
    float* Wsm = sm;                 // 33280
    float* ins = sm + CV2_WF;        // 23040
    int blk = blockIdx.x;
    int s = blk >> 4;
    int b0 = (blk & 15) * 8;
    int t = threadIdx.x;
    int lane = t & 31, w = t >> 5;
    int g = lane >> 2, tig = lane & 3;

    // cooperative loads (weights verbatim; input tf32-rounded at load)
    {
        const float4* wp = (const float4*)(g_w2p + (long)s * 33280);
        float4* wd = (float4*)Wsm;
        for (int j = t; j < 8320; j += 512) wd[j] = wp[j];
        const float4* ip = (const float4*)(g_h1 + (long)(s * BATCH + b0) * 2880);
        float4* id = (float4*)ins;
        for (int j = t; j < 5760; j += 512) {
            float4 v = ip[j];
            v.x = __uint_as_float(f2tf32(v.x));
            v.y = __uint_as_float(f2tf32(v.y));
            v.z = __uint_as_float(f2tf32(v.z));
            v.w = __uint_as_float(f2tf32(v.w));
            id[j] = v;
        }
    }

    int m0 = (w & 1) * 32;
    int n0 = (w >> 1) * 64;

    // A row indices (clamp to zero column 50 for m >= 50)
    int mA[2][2];
#pragma unroll
    for (int mt = 0; mt < 2; mt++) {
        int r0 = m0 + mt * 16 + g;
        int r1 = r0 + 8;
        mA[mt][0] = (r0 < 50) ? r0 : 50;
        mA[mt][1] = (r1 < 50) ? r1 : 50;
    }

    // B gather bases: column c = n0 + nt*8 + g -> (img, y, x)
    int rowbase[8];
#pragma unroll
    for (int nt = 0; nt < 8; nt++) {
        int c = n0 + nt * 8 + g;
        int img = c >> 6, y = (c >> 3) & 7, xx = c & 7;
        rowbase[nt] = img * 2880 + y * 12 + xx;
    }
    // filter offsets per kt (k-row = kt*8+tig and +4); invalid rows clamp to 0
    int off0[4], off1[4];
#pragma unroll
    for (int kt = 0; kt < 4; kt++) {
        int kk0 = kt * 8 + tig;
        off0[kt] = (kk0 <= 24) ? (kk0 / 5) * 12 + (kk0 % 5) : 0;
        int kk1 = kk0 + 4;
        off1[kt] = (kk1 <= 24) ? (kk1 / 5) * 12 + (kk1 % 5) : 0;
    }

    float acc[2][8][4];
#pragma unroll
    for (int mt = 0; mt < 2; mt++)
#pragma unroll
        for (int nt = 0; nt < 8; nt++)
#pragma unroll
            for (int q = 0; q < 4; q++) acc[mt][nt][q] = 0.0f;

    __syncthreads();

#pragma unroll 1
    for (int ci = 0; ci < 20; ci++) {
        int cib = ci * 144;
#pragma unroll
        for (int kt = 0; kt < 4; kt++) {
            const float* Wk = Wsm + (ci * 32 + kt * 8 + tig) * 52;
            uint32_t a[2][4];
#pragma unroll
            for (int mt = 0; mt < 2; mt++) {
                a[mt][0] = __float_as_uint(Wk[mA[mt][0]]);
                a[mt][1] = __float_as_uint(Wk[mA[mt][1]]);
                a[mt][2] = __float_as_uint(Wk[4 * 52 + mA[mt][0]]);
                a[mt][3] = __float_as_uint(Wk[4 * 52 + mA[mt][1]]);
            }
            const float* insc = ins + cib;
#pragma unroll
            for (int nt = 0; nt < 8; nt++) {
                uint32_t br0 = __float_as_uint(insc[rowbase[nt] + off0[kt]]);
                uint32_t br1 = __float_as_uint(insc[rowbase[nt] + off1[kt]]);
#pragma unroll
                for (int mt = 0; mt < 2; mt++) {
                    asm volatile(
                        "mma.sync.aligned.m16n8k8.row.col.f32.tf32.tf32.f32 "
                        "{%0,%1,%2,%3}, {%4,%5,%6,%7}, {%8,%9}, {%0,%1,%2,%3};\n"
                        : "+f"(acc[mt][nt][0]), "+f"(acc[mt][nt][1]),
                          "+f"(acc[mt][nt][2]), "+f"(acc[mt][nt][3])
                        : "r"(a[mt][0]), "r"(a[mt][1]), "r"(a[mt][2]), "r"(a[mt][3]),
                          "r"(br0), "r"(br1));
                }
            }
        }
    }

    // epilogue: C -> smem (reuse Wsm; all W reads done), then bias+relu+maxpool
    __syncthreads();
    float* Csm = Wsm;   // [64][520]
#pragma unroll
    for (int mt = 0; mt < 2; mt++) {
        int r0 = m0 + mt * 16 + g;
#pragma unroll
        for (int nt = 0; nt < 8; nt++) {
            int c0 = n0 + nt * 8 + 2 * tig;
            Csm[r0 * 520 + c0]           = acc[mt][nt][0];
            Csm[r0 * 520 + c0 + 1]       = acc[mt][nt][1];
            Csm[(r0 + 8) * 520 + c0]     = acc[mt][nt][2];
            Csm[(r0 + 8) * 520 + c0 + 1] = acc[mt][nt][3];
        }
    }
    __syncthreads();

    for (int idx = t; idx < 6400; idx += 512) {
        int ch = idx >> 7;        // 50 channels x 128 (8 img x 16 pooled px)
        int r = idx & 127;
        int img = r >> 4;
        int pp = r & 15;
        int py = pp >> 2, px = pp & 3;
        int n = img * 64 + (2 * py) * 8 + 2 * px;
        float v0 = Csm[ch * 520 + n],       v1 = Csm[ch * 520 + n + 1];
        float v2 = Csm[ch * 520 + n + 8],   v3 = Csm[ch * 520 + n + 9];
        float v = fmaxf(fmaxf(v0, v1), fmaxf(v2, v3)) + g_ball[s * NB + 20 + ch];
        g_h2[(long)(s * BATCH + b0 + img) * 800 + ch * 16 + pp] = fmaxf(v, 0.0f);
    }
}

// ---------------- kernel 4: fc1 (500x800 @ 800x128) + bias + relu ----------------
__global__ void __launch_bounds__(256) k_fc1(const float* __restrict__ e,
                                             const float* __restrict__ mu_w) {
    __shared__ float As[8][68];
    __shared__ float Bs[8][128];
    int s = blockIdx.y;
    int mt = blockIdx.x;
    int tid = threadIdx.x;
    int tx = tid % 16, ty = tid / 16;
    int m0 = mt * 64;

    const float* eb = e + (long)s * ES + WOFF2;

    int la = tid * 2;
    int am = la / 8, ak = la % 8;
    int bn = tid / 2, bq = (tid % 2) * 4;

    float ra0, ra1;
    float rb0, rb1, rb2, rb3;
    {
        int grow = m0 + am;
        if (grow < 500) {
            long ai = (long)grow * 800 + ak;
            ra0 = fmaf(g_sigw[WOFF2 + ai], eb[ai], mu_w[WOFF2 + ai]);
            ra1 = fmaf(g_sigw[WOFF2 + ai + 1], eb[ai + 1], mu_w[WOFF2 + ai + 1]);
        } else { ra0 = 0.0f; ra1 = 0.0f; }
        float4 bv = *(const float4*)(g_h2 + ((long)s * BATCH + bn) * 800 + bq);
        rb0 = bv.x; rb1 = bv.y; rb2 = bv.z; rb3 = bv.w;
    }

    float acc[4][8];
#pragma unroll
    for (int i = 0; i < 4; i++)
#pragma unroll
        for (int j = 0; j < 8; j++) acc[i][j] = 0.0f;

    for (int kt = 0; kt < 100; kt++) {
        As[ak][am] = ra0;
        As[ak + 1][am] = ra1;
        Bs[bq + 0][bn] = rb0;
        Bs[bq + 1][bn] = rb1;
        Bs[bq + 2][bn] = rb2;
        Bs[bq + 3][bn] = rb3;
        __syncthreads();

        if (kt < 99) {
            int k0 = (kt + 1) * 8;
            int grow = m0 + am;
            if (grow < 500) {
                long ai = (long)grow * 800 + k0 + ak;
                ra0 = fmaf(g_sigw[WOFF2 + ai], eb[ai], mu_w[WOFF2 + ai]);
                ra1 = fmaf(g_sigw[WOFF2 + ai + 1], eb[ai + 1], mu_w[WOFF2 + ai + 1]);
            } else { ra0 = 0.0f; ra1 = 0.0f; }
            float4 bv = *(const float4*)(g_h2 + ((long)s * BATCH + bn) * 800 + k0 + bq);
            rb0 = bv.x; rb1 = bv.y; rb2 = bv.z; rb3 = bv.w;
        }

#pragma unroll
        for (int k = 0; k < 8; k++) {
            float a[4], bb[8];
            *(float4*)a = *(const float4*)&As[k][ty * 4];
            *(float4*)bb = *(const float4*)&Bs[k][tx * 8];
            *(float4*)(bb + 4) = *(const float4*)&Bs[k][tx * 8 + 4];
#pragma unroll
            for (int i = 0; i < 4; i++)
#pragma unroll
                for (int j = 0; j < 8; j++)
                    acc[i][j] = fmaf(a[i], bb[j], acc[i][j]);
        }
        __syncthreads();
    }

#pragma unroll
    for (int i = 0; i < 4; i++) {
        int m = m0 + ty * 4 + i;
        if (m < 500) {
            float bias = g_ball[s * NB + 70 + m];
            float* op = g_h3 + ((long)s * 500 + m) * BATCH + tx * 8;
#pragma unroll
            for (int j = 0; j < 8; j++) {
                op[j] = fmaxf(acc[i][j] + bias, 0.0f);
            }
        }
    }
}

// ---------------- kernel 5: fc2 + bias + log_softmax ----------------
__global__ void __launch_bounds__(128) k_fc2(const float* __restrict__ e,
                                             const float* __restrict__ mu_w) {
    __shared__ float ws[5000];
    __shared__ float bs[10];
    int s = blockIdx.x;
    int t = threadIdx.x;
    for (int j = t; j < 5000; j += 128) {
        long gi = (long)WOFF3 + j;
        ws[j] = fmaf(g_sigw[gi], e[(long)s * ES + gi], mu_w[gi]);
    }
    if (t < 10) bs[t] = g_ball[s * NB + 570 + t];
    __syncthreads();

    float acc[10];
#pragma unroll
    for (int o = 0; o < 10; o++) acc[o] = bs[o];

    const float* hp = g_h3 + (long)s * 500 * BATCH + t;
    for (int i = 0; i < 500; i++) {
        float v = hp[(long)i * BATCH];
#pragma unroll
        for (int o = 0; o < 10; o++) acc[o] = fmaf(ws[o * 500 + i], v, acc[o]);
    }

    float m = acc[0];
#pragma unroll
    for (int o = 1; o < 10; o++) m = fmaxf(m, acc[o]);
    float sum = 0.0f;
#pragma unroll
    for (int o = 0; o < 10; o++) sum += expf(acc[o] - m);
    float lse = m + logf(sum);

    float* op = g_lsm + ((long)s * BATCH + t) * 10;
#pragma unroll
    for (int o = 0; o < 10; o++) op[o] = acc[o] - lse;
}

// ---------------- kernel 6: deterministic mean over samples ----------------
__global__ void k_reduce(float* __restrict__ out) {
    int idx = blockIdx.x * blockDim.x + threadIdx.x;
    if (idx >= BATCH * 10) return;
    int b = idx / 10, o = idx % 10;
    float acc = 0.0f;
    for (int s = 0; s < S; s++) acc += g_lsm[((long)s * BATCH + b) * 10 + o];
    out[idx] = acc * (1.0f / (float)S);
}

// ---------------- launch ----------------
extern "C" void kernel_launch(void* const* d_in, const int* in_sizes, int n_in,
                              void* d_out, int out_size) {
    const float* x     = (const float*)d_in[0];
    const float* e     = (const float*)d_in[1];
    const float* mu_w  = (const float*)d_in[2];
    const float* rho_w = (const float*)d_in[3];
    const float* mu_b  = (const float*)d_in[4];
    const float* rho_b = (const float*)d_in[5];
    float* out = (float*)d_out;

    static int smem_set = 0;
    if (!smem_set) {
        cudaFuncSetAttribute(k_conv2_tc, cudaFuncAttributeMaxDynamicSharedMemorySize,
                             CV2T_SMEM);
        smem_set = 1;
    }

    k_sig<<<(ES + 255) / 256, 256>>>(rho_w, rho_b);

    int wb_total = S * W12N + S * NB;
    k_wb<<<(wb_total + 255) / 256, 256>>>(e, mu_w, mu_b);

    k_conv1<<<S * BATCH, 288>>>(x);
    k_conv2_tc<<<S * 16, 512, CV2T_SMEM>>>();

    dim3 g1(8, S);
    k_fc1<<<g1, 256>>>(e, mu_w);
    k_fc2<<<S, 128>>>(e, mu_w);
    k_reduce<<<10, 128>>>(out);
}

// round 10
// speedup vs baseline: 2.6697x; 1.3061x over previous
#include <cuda_runtime.h>
#include <math.h>
#include <stdint.h>

#define S 100
#define BATCH 128
#define NW 430500
#define NB 580
#define ES (NW + NB)
#define W12N 25500
#define WOFF2 25500
#define WOFF3 425500

// ---------------- scratch (device globals; no runtime allocation) ----------------
__device__ float g_sigw[NW];
__device__ float g_sigb[NB];
__device__ float g_w1[S * 500];           // per-sample conv1 weights
__device__ float g_w2p[S * 33280];        // per-sample conv2 weights, [k=ci*32+kk][52 ch pad], tf32-rounded
__device__ float g_ball[S * NB];          // per-sample all biases
__device__ float g_h1[S * BATCH * 2880];  // after conv1+relu+pool: [s][b][20][12][12]
__device__ float g_h2[S * BATCH * 800];   // after conv2+relu+pool: [s][b][800] (c*16+y*4+x)
__device__ float g_h3[S * 500 * BATCH];   // after fc1+relu: [s][500][128]
__device__ float g_lsm[S * BATCH * 10];   // per-sample log-softmax

__device__ __forceinline__ float softplusf(float r) {
    return fmaxf(r, 0.0f) + log1pf(expf(-fabsf(r)));
}

__device__ __forceinline__ uint32_t f2tf32(float v) {
    uint32_t o;
    asm("cvt.rna.tf32.f32 %0, %1;" : "=r"(o) : "f"(v));
    return o;
}

// ---------------- kernel 0: softplus(rho) ----------------
__global__ void k_sig(const float* __restrict__ rho_w, const float* __restrict__ rho_b) {
    int i = blockIdx.x * blockDim.x + threadIdx.x;
    if (i < NW) g_sigw[i] = softplusf(rho_w[i]);
    else if (i < NW + NB) g_sigb[i - NW] = softplusf(rho_b[i - NW]);
}

// ---------------- kernel 1: materialize conv weights + biases ----------------
__global__ void k_wb(const float* __restrict__ e,
                     const float* __restrict__ mu_w,
                     const float* __restrict__ mu_b) {
    int i = blockIdx.x * blockDim.x + threadIdx.x;
    if (i < S * W12N) {
        int s = i / W12N, j = i % W12N;
        float v = fmaf(g_sigw[j], e[(long)s * ES + j], mu_w[j]);
        if (j < 500) {
            g_w1[s * 500 + j] = v;
        } else {
            int jj = j - 500;
            int ch = jj / 500;
            int r = jj % 500;
            int ci = r / 25, wo = r % 25;
            g_w2p[(long)s * 33280 + (ci * 32 + wo) * 52 + ch] = __uint_as_float(f2tf32(v));
        }
    } else {
        int r = i - S * W12N;
        if (r < S * NB) {
            int s = r / NB, j = r % NB;
            g_ball[r] = fmaf(g_sigb[j], e[(long)s * ES + NW + j], mu_b[j]);
        }
    }
}

// ---------------- kernel 2: conv1 + bias + relu + maxpool ----------------
__global__ void __launch_bounds__(288) k_conv1(const float* __restrict__ x) {
    __shared__ float xs[784];
    __shared__ float ws[500];
    __shared__ float bs[20];
    int blk = blockIdx.x;
    int s = blk / BATCH, b = blk % BATCH;
    int t = threadIdx.x;
    for (int j = t; j < 784; j += 288) xs[j] = x[b * 784 + j];
    for (int j = t; j < 500; j += 288) ws[j] = g_w1[s * 500 + j];
    if (t < 20) bs[t] = g_ball[s * NB + t];
    __syncthreads();

    int pp = t % 144, cg = t / 144;
    int pi = pp / 12, pj = pp % 12;
    float acc[10][4];
#pragma unroll
    for (int k = 0; k < 10; k++) { acc[k][0] = acc[k][1] = acc[k][2] = acc[k][3] = 0.0f; }

    const float* xb = xs + (2 * pi) * 28 + 2 * pj;
#pragma unroll 1
    for (int ky = 0; ky < 5; ky++) {
#pragma unroll
        for (int kx = 0; kx < 5; kx++) {
            float i00 = xb[ky * 28 + kx];
            float i01 = xb[ky * 28 + kx + 1];
            float i10 = xb[(ky + 1) * 28 + kx];
            float i11 = xb[(ky + 1) * 28 + kx + 1];
#pragma unroll
            for (int k = 0; k < 10; k++) {
                float wv = ws[(cg * 10 + k) * 25 + ky * 5 + kx];
                acc[k][0] = fmaf(wv, i00, acc[k][0]);
                acc[k][1] = fmaf(wv, i01, acc[k][1]);
                acc[k][2] = fmaf(wv, i10, acc[k][2]);
                acc[k][3] = fmaf(wv, i11, acc[k][3]);
            }
        }
    }
    float* outp = g_h1 + (long)(s * BATCH + b) * 2880;
#pragma unroll
    for (int k = 0; k < 10; k++) {
        int c = cg * 10 + k;
        float v = fmaxf(fmaxf(acc[k][0], acc[k][1]), fmaxf(acc[k][2], acc[k][3])) + bs[c];
        outp[c * 144 + pp] = fmaxf(v, 0.0f);
    }
}

// ---------------- kernel 3: conv2 tf32 implicit GEMM, direct B gather ----------------
#define CV2_WF (640 * 52)
#define CV2_IF (8 * 2880)
#define CV2T_SMEM ((CV2_WF + CV2_IF) * 4)

__global__ void __launch_bounds__(512) k_conv2_tc() {
    extern __shared__ float sm[];
    float* Wsm = sm;                 // 33280
    float* ins = sm + CV2_WF;        // 23040
    int blk = blockIdx.x;
    int s = blk >> 4;
    int b0 = (blk & 15) * 8;
    int t = threadIdx.x;
    int lane = t & 31, w = t >> 5;
    int g = lane >> 2, tig = lane & 3;

    {
        const float4* wp = (const float4*)(g_w2p + (long)s * 33280);
        float4* wd = (float4*)Wsm;
        for (int j = t; j < 8320; j += 512) wd[j] = wp[j];
        const float4* ip = (const float4*)(g_h1 + (long)(s * BATCH + b0) * 2880);
        float4* id = (float4*)ins;
        for (int j = t; j < 5760; j += 512) {
            float4 v = ip[j];
            v.x = __uint_as_float(f2tf32(v.x));
            v.y = __uint_as_float(f2tf32(v.y));
            v.z = __uint_as_float(f2tf32(v.z));
            v.w = __uint_as_float(f2tf32(v.w));
            id[j] = v;
        }
    }

    int m0 = (w & 1) * 32;
    int n0 = (w >> 1) * 64;

    int mA[2][2];
#pragma unroll
    for (int mt = 0; mt < 2; mt++) {
        int r0 = m0 + mt * 16 + g;
        int r1 = r0 + 8;
        mA[mt][0] = (r0 < 50) ? r0 : 50;
        mA[mt][1] = (r1 < 50) ? r1 : 50;
    }

    int rowbase[8];
#pragma unroll
    for (int nt = 0; nt < 8; nt++) {
        int c = n0 + nt * 8 + g;
        int img = c >> 6, y = (c >> 3) & 7, xx = c & 7;
        rowbase[nt] = img * 2880 + y * 12 + xx;
    }
    int off0[4], off1[4];
#pragma unroll
    for (int kt = 0; kt < 4; kt++) {
        int kk0 = kt * 8 + tig;
        off0[kt] = (kk0 <= 24) ? (kk0 / 5) * 12 + (kk0 % 5) : 0;
        int kk1 = kk0 + 4;
        off1[kt] = (kk1 <= 24) ? (kk1 / 5) * 12 + (kk1 % 5) : 0;
    }

    float acc[2][8][4];
#pragma unroll
    for (int mt = 0; mt < 2; mt++)
#pragma unroll
        for (int nt = 0; nt < 8; nt++)
#pragma unroll
            for (int q = 0; q < 4; q++) acc[mt][nt][q] = 0.0f;

    __syncthreads();

#pragma unroll 1
    for (int ci = 0; ci < 20; ci++) {
        int cib = ci * 144;
#pragma unroll
        for (int kt = 0; kt < 4; kt++) {
            const float* Wk = Wsm + (ci * 32 + kt * 8 + tig) * 52;
            uint32_t a[2][4];
#pragma unroll
            for (int mt = 0; mt < 2; mt++) {
                a[mt][0] = __float_as_uint(Wk[mA[mt][0]]);
                a[mt][1] = __float_as_uint(Wk[mA[mt][1]]);
                a[mt][2] = __float_as_uint(Wk[4 * 52 + mA[mt][0]]);
                a[mt][3] = __float_as_uint(Wk[4 * 52 + mA[mt][1]]);
            }
            const float* insc = ins + cib;
#pragma unroll
            for (int nt = 0; nt < 8; nt++) {
                uint32_t br0 = __float_as_uint(insc[rowbase[nt] + off0[kt]]);
                uint32_t br1 = __float_as_uint(insc[rowbase[nt] + off1[kt]]);
#pragma unroll
                for (int mt = 0; mt < 2; mt++) {
                    asm volatile(
                        "mma.sync.aligned.m16n8k8.row.col.f32.tf32.tf32.f32 "
                        "{%0,%1,%2,%3}, {%4,%5,%6,%7}, {%8,%9}, {%0,%1,%2,%3};\n"
                        : "+f"(acc[mt][nt][0]), "+f"(acc[mt][nt][1]),
                          "+f"(acc[mt][nt][2]), "+f"(acc[mt][nt][3])
                        : "r"(a[mt][0]), "r"(a[mt][1]), "r"(a[mt][2]), "r"(a[mt][3]),
                          "r"(br0), "r"(br1));
                }
            }
        }
    }

    __syncthreads();
    float* Csm = Wsm;   // [64][520]
#pragma unroll
    for (int mt = 0; mt < 2; mt++) {
        int r0 = m0 + mt * 16 + g;
#pragma unroll
        for (int nt = 0; nt < 8; nt++) {
            int c0 = n0 + nt * 8 + 2 * tig;
            Csm[r0 * 520 + c0]           = acc[mt][nt][0];
            Csm[r0 * 520 + c0 + 1]       = acc[mt][nt][1];
            Csm[(r0 + 8) * 520 + c0]     = acc[mt][nt][2];
            Csm[(r0 + 8) * 520 + c0 + 1] = acc[mt][nt][3];
        }
    }
    __syncthreads();

    for (int idx = t; idx < 6400; idx += 512) {
        int ch = idx >> 7;
        int r = idx & 127;
        int img = r >> 4;
        int pp = r & 15;
        int py = pp >> 2, px = pp & 3;
        int n = img * 64 + (2 * py) * 8 + 2 * px;
        float v0 = Csm[ch * 520 + n],       v1 = Csm[ch * 520 + n + 1];
        float v2 = Csm[ch * 520 + n + 8],   v3 = Csm[ch * 520 + n + 9];
        float v = fmaxf(fmaxf(v0, v1), fmaxf(v2, v3)) + g_ball[s * NB + 20 + ch];
        g_h2[(long)(s * BATCH + b0 + img) * 800 + ch * 16 + pp] = fmaxf(v, 0.0f);
    }
}

// ---------------- kernel 4: fc1 as tf32 tensor-core GEMM ----------------
// grid = (4 mtiles, S), block = 256 (8 warps, 4m x 2n), warp tile 32x64.
// C[128][128] = A[128][800] x B[800][128]; K chunks of 32.
// A generated on the fly (mu + sig*e, tf32), B from g_h2 transposed to [k][n].
// smem: A [128][44] = 5632 fl, B [32][132] = 4224 fl -> ~39 KB.
#define FC1_APAD 44
#define FC1_BPAD 132
__global__ void __launch_bounds__(256) k_fc1_tc(const float* __restrict__ e,
                                                const float* __restrict__ mu_w) {
    __shared__ float As[128 * FC1_APAD];
    __shared__ float Bs[32 * FC1_BPAD];
    int s = blockIdx.y;
    int m0blk = blockIdx.x * 128;
    int t = threadIdx.x;
    int lane = t & 31, w = t >> 5;
    int g = lane >> 2, tig = lane & 3;
    int wm0 = (w & 3) * 32;
    int wn0 = (w >> 2) * 64;

    const float* eb  = e + (long)s * ES + WOFF2;
    const float* mwb = mu_w + WOFF2;
    const float* sgb = g_sigw + WOFF2;
    const float* h2b = g_h2 + (long)s * BATCH * 800;

    float acc[2][8][4];
#pragma unroll
    for (int mt = 0; mt < 2; mt++)
#pragma unroll
        for (int nt = 0; nt < 8; nt++)
#pragma unroll
            for (int q = 0; q < 4; q++) acc[mt][nt][q] = 0.0f;

#pragma unroll 1
    for (int kc = 0; kc < 25; kc++) {
        int k0 = kc * 32;
        // generate A chunk [128 m][32 k]
#pragma unroll
        for (int jj = t; jj < 1024; jj += 256) {
            int m = jj >> 3, kq = jj & 7;
            int grow = m0blk + m;
            float4 v = {0.0f, 0.0f, 0.0f, 0.0f};
            if (grow < 500) {
                long ai = (long)grow * 800 + k0 + kq * 4;
                float4 sg = *(const float4*)(sgb + ai);
                float4 ev = *(const float4*)(eb + ai);
                float4 mv = *(const float4*)(mwb + ai);
                v.x = __uint_as_float(f2tf32(fmaf(sg.x, ev.x, mv.x)));
                v.y = __uint_as_float(f2tf32(fmaf(sg.y, ev.y, mv.y)));
                v.z = __uint_as_float(f2tf32(fmaf(sg.z, ev.z, mv.z)));
                v.w = __uint_as_float(f2tf32(fmaf(sg.w, ev.w, mv.w)));
            }
            *(float4*)(As + m * FC1_APAD + kq * 4) = v;
        }
        // load B chunk: h2[n][k0..k0+31] -> Bs[k][n]
#pragma unroll
        for (int jj = t; jj < 1024; jj += 256) {
            int n = jj >> 3, kq = jj & 7;
            float4 v = *(const float4*)(h2b + (long)n * 800 + k0 + kq * 4);
            Bs[(kq * 4 + 0) * FC1_BPAD + n] = __uint_as_float(f2tf32(v.x));
            Bs[(kq * 4 + 1) * FC1_BPAD + n] = __uint_as_float(f2tf32(v.y));
            Bs[(kq * 4 + 2) * FC1_BPAD + n] = __uint_as_float(f2tf32(v.z));
            Bs[(kq * 4 + 3) * FC1_BPAD + n] = __uint_as_float(f2tf32(v.w));
        }
        __syncthreads();

#pragma unroll
        for (int kt = 0; kt < 4; kt++) {
            uint32_t a[2][4];
#pragma unroll
            for (int mt = 0; mt < 2; mt++) {
                const float* Ar = As + (wm0 + mt * 16 + g) * FC1_APAD + kt * 8 + tig;
                a[mt][0] = __float_as_uint(Ar[0]);
                a[mt][1] = __float_as_uint(Ar[8 * FC1_APAD]);
                a[mt][2] = __float_as_uint(Ar[4]);
                a[mt][3] = __float_as_uint(Ar[8 * FC1_APAD + 4]);
            }
            const float* Bk = Bs + (kt * 8 + tig) * FC1_BPAD + wn0 + g;
#pragma unroll
            for (int nt = 0; nt < 8; nt++) {
                uint32_t br0 = __float_as_uint(Bk[nt * 8]);
                uint32_t br1 = __float_as_uint(Bk[4 * FC1_BPAD + nt * 8]);
#pragma unroll
                for (int mt = 0; mt < 2; mt++) {
                    asm volatile(
                        "mma.sync.aligned.m16n8k8.row.col.f32.tf32.tf32.f32 "
                        "{%0,%1,%2,%3}, {%4,%5,%6,%7}, {%8,%9}, {%0,%1,%2,%3};\n"
                        : "+f"(acc[mt][nt][0]), "+f"(acc[mt][nt][1]),
                          "+f"(acc[mt][nt][2]), "+f"(acc[mt][nt][3])
                        : "r"(a[mt][0]), "r"(a[mt][1]), "r"(a[mt][2]), "r"(a[mt][3]),
                          "r"(br0), "r"(br1));
                }
            }
        }
        __syncthreads();
    }

    // epilogue: bias + relu -> g_h3[s][m][n]
#pragma unroll
    for (int mt = 0; mt < 2; mt++) {
#pragma unroll
        for (int half = 0; half < 2; half++) {
            int m = m0blk + wm0 + mt * 16 + half * 8 + g;
            if (m < 500) {
                float bias = g_ball[s * NB + 70 + m];
                float* op = g_h3 + ((long)s * 500 + m) * BATCH;
#pragma unroll
                for (int nt = 0; nt < 8; nt++) {
                    int c0 = wn0 + nt * 8 + 2 * tig;
                    op[c0]     = fmaxf(acc[mt][nt][half * 2]     + bias, 0.0f);
                    op[c0 + 1] = fmaxf(acc[mt][nt][half * 2 + 1] + bias, 0.0f);
                }
            }
        }
    }
}

// ---------------- kernel 5: fc2 + bias + log_softmax ----------------
__global__ void __launch_bounds__(128) k_fc2(const float* __restrict__ e,
                                             const float* __restrict__ mu_w) {
    __shared__ float ws[5000];
    __shared__ float bs[10];
    int s = blockIdx.x;
    int t = threadIdx.x;
    for (int j = t; j < 5000; j += 128) {
        long gi = (long)WOFF3 + j;
        ws[j] = fmaf(g_sigw[gi], e[(long)s * ES + gi], mu_w[gi]);
    }
    if (t < 10) bs[t] = g_ball[s * NB + 570 + t];
    __syncthreads();

    float acc[10];
#pragma unroll
    for (int o = 0; o < 10; o++) acc[o] = bs[o];

    const float* hp = g_h3 + (long)s * 500 * BATCH + t;
    for (int i = 0; i < 500; i++) {
        float v = hp[(long)i * BATCH];
#pragma unroll
        for (int o = 0; o < 10; o++) acc[o] = fmaf(ws[o * 500 + i], v, acc[o]);
    }

    float m = acc[0];
#pragma unroll
    for (int o = 1; o < 10; o++) m = fmaxf(m, acc[o]);
    float sum = 0.0f;
#pragma unroll
    for (int o = 0; o < 10; o++) sum += expf(acc[o] - m);
    float lse = m + logf(sum);

    float* op = g_lsm + ((long)s * BATCH + t) * 10;
#pragma unroll
    for (int o = 0; o < 10; o++) op[o] = acc[o] - lse;
}

// ---------------- kernel 6: deterministic mean over samples ----------------
__global__ void k_reduce(float* __restrict__ out) {
    int idx = blockIdx.x * blockDim.x + threadIdx.x;
    if (idx >= BATCH * 10) return;
    int b = idx / 10, o = idx % 10;
    float acc = 0.0f;
    for (int s = 0; s < S; s++) acc += g_lsm[((long)s * BATCH + b) * 10 + o];
    out[idx] = acc * (1.0f / (float)S);
}

// ---------------- launch ----------------
extern "C" void kernel_launch(void* const* d_in, const int* in_sizes, int n_in,
                              void* d_out, int out_size) {
    const float* x     = (const float*)d_in[0];
    const float* e     = (const float*)d_in[1];
    const float* mu_w  = (const float*)d_in[2];
    const float* rho_w = (const float*)d_in[3];
    const float* mu_b  = (const float*)d_in[4];
    const float* rho_b = (const float*)d_in[5];
    float* out = (float*)d_out;

    static int smem_set = 0;
    if (!smem_set) {
        cudaFuncSetAttribute(k_conv2_tc, cudaFuncAttributeMaxDynamicSharedMemorySize,
                             CV2T_SMEM);
        smem_set = 1;
    }

    k_sig<<<(ES + 255) / 256, 256>>>(rho_w, rho_b);

    int wb_total = S * W12N + S * NB;
    k_wb<<<(wb_total + 255) / 256, 256>>>(e, mu_w, mu_b);

    k_conv1<<<S * BATCH, 288>>>(x);
    k_conv2_tc<<<S * 16, 512, CV2T_SMEM>>>();

    dim3 g1(4, S);
    k_fc1_tc<<<g1, 256>>>(e, mu_w);
    k_fc2<<<S, 128>>>(e, mu_w);
    k_reduce<<<10, 128>>>(out);
}